// round 5
// baseline (speedup 1.0000x reference)
#include <cuda_runtime.h>
#include <cuda_fp16.h>
#include <cuda_fp8.h>
#include <cstdint>

// ============================================================================
// Toolchain targets plain sm_100 (no 'a') — tcgen05/TMA-tensor unavailable.
// Supported path: cp.async + ldmatrix + mma.sync.m16n8k16 (fp16 in, f32 acc).
// ============================================================================

// Problem constants (dataset shapes: M=16384, K=H=2048, N=O=2048)
static constexpr int GK   = 2048;
static constexpr int GN   = 2048;
static constexpr int MAXM = 16384;

// Exact power-of-two pre-scales keep fp16 operands in the normal range.
// A *= 2^6, B *= 2^10, epilogue *= 2^-16 (all exact).
static constexpr float A_SCALE   = 64.0f;
static constexpr float B_SCALE   = 1024.0f;
static constexpr float OUT_SCALE = 1.0f / 65536.0f;

// Scratch (static device allocations are allowed)
__device__ __align__(128) __half g_xdq[(size_t)MAXM * GK];   // 64 MB
__device__ __align__(128) __half g_wdq[(size_t)GN * GK];     //  8 MB

#define SMEM_SWIZZLE_128B(byte_offset) \
    ((byte_offset) ^ (((byte_offset) >> 3) & 0x70))

__device__ __forceinline__ uint32_t smem_to_u32(const void* smem_ptr) {
    uint32_t addr;
    asm("{ .reg .u64 tmp; cvta.to.shared.u64 tmp, %1; cvt.u32.u64 %0, tmp; }"
        : "=r"(addr) : "l"(smem_ptr));
    return addr;
}

// ============================================================================
// Kernel 1: per-token-group fp8 quantize + dequantize x -> fp16 (x 2^6)
// One warp per 128-element group.
// ============================================================================
__global__ __launch_bounds__(256) void quant_x_kernel(
    const float* __restrict__ x, int ngroups
) {
    int g = blockIdx.x * 8 + (threadIdx.x >> 5);
    if (g >= ngroups) return;
    int lane = threadIdx.x & 31;

    const float4 v = reinterpret_cast<const float4*>(x + (size_t)g * 128)[lane];
    float m = fmaxf(fmaxf(fabsf(v.x), fabsf(v.y)), fmaxf(fabsf(v.z), fabsf(v.w)));
    #pragma unroll
    for (int o = 16; o > 0; o >>= 1)
        m = fmaxf(m, __shfl_xor_sync(0xffffffffu, m, o));
    m = fmaxf(m, 1e-12f);

    float s   = 448.0f / m;
    float inv = (1.0f / s) * A_SCALE;

    float r[4] = {v.x, v.y, v.z, v.w};
    __half h[4];
    #pragma unroll
    for (int i = 0; i < 4; i++) {
        float q  = fminf(fmaxf(r[i] * s, -448.0f), 448.0f);
        float dq = float(__nv_fp8_e4m3(q)) * inv;   // exact fp8 RTNE round-trip
        h[i] = __float2half_rn(dq);
    }
    __half2* dst = reinterpret_cast<__half2*>(g_xdq + (size_t)g * 128);
    dst[lane * 2]     = __halves2half2(h[0], h[1]);
    dst[lane * 2 + 1] = __halves2half2(h[2], h[3]);
}

// ============================================================================
// Kernel 2: weight dequant -> fp16 (x 2^10)
// ============================================================================
__global__ __launch_bounds__(256) void dequant_w_kernel(
    const float* __restrict__ w, const float* __restrict__ ws
) {
    int i = blockIdx.x * blockDim.x + threadIdx.x;       // quad index
    if (i >= GN * GK / 4) return;
    float4 v = reinterpret_cast<const float4*>(w)[i];
    int base = i * 4;
    int n = base >> 11;
    int k = base & (GK - 1);
    float s = ws[((n >> 7) * (GK / 128)) + (k >> 7)] * B_SCALE;
    __half2* dst = reinterpret_cast<__half2*>(g_wdq);
    dst[i * 2]     = __halves2half2(__float2half_rn(v.x * s), __float2half_rn(v.y * s));
    dst[i * 2 + 1] = __halves2half2(__float2half_rn(v.z * s), __float2half_rn(v.w * s));
}

// ============================================================================
// Kernel 3: fp16 mma.sync GEMM.  D[m][n] = sum_k A[m][k]*B[n][k]
// CTA tile 128x128, BK=64, 3-stage cp.async, 8 warps @ 64x32 warp tile.
// Smem rows are 128B (64 halfs) with SW128 xor swizzle; ldmatrix (no trans)
// serves both A and B fragments since both are K-major.
// ============================================================================
static constexpr int BM = 128;
static constexpr int BN = 128;
static constexpr int BK = 64;
static constexpr int STAGES = 3;

static constexpr int A_STAGE_B = BM * 128;   // 16 KB
static constexpr int B_STAGE_B = BN * 128;   // 16 KB
static constexpr int STAGE_B   = A_STAGE_B + B_STAGE_B;      // 32 KB
static constexpr int SMEM_TOTAL = STAGES * STAGE_B;           // 96 KB

__device__ __forceinline__ void cp16(uint32_t dst, const void* src) {
    asm volatile("cp.async.cg.shared.global [%0], [%1], 16;\n"
                 :: "r"(dst), "l"(src));
}

__device__ __forceinline__ void ldsm4(uint32_t& r0, uint32_t& r1,
                                      uint32_t& r2, uint32_t& r3, uint32_t addr) {
    asm volatile("ldmatrix.sync.aligned.m8n8.x4.shared.b16 {%0,%1,%2,%3}, [%4];"
                 : "=r"(r0), "=r"(r1), "=r"(r2), "=r"(r3) : "r"(addr));
}

__device__ __forceinline__ void mma16816(float* d,
                                         uint32_t a0, uint32_t a1, uint32_t a2, uint32_t a3,
                                         uint32_t b0, uint32_t b1) {
    asm volatile(
        "mma.sync.aligned.m16n8k16.row.col.f32.f16.f16.f32 "
        "{%0,%1,%2,%3}, {%4,%5,%6,%7}, {%8,%9}, {%0,%1,%2,%3};"
        : "+f"(d[0]), "+f"(d[1]), "+f"(d[2]), "+f"(d[3])
        : "r"(a0), "r"(a1), "r"(a2), "r"(a3), "r"(b0), "r"(b1));
}

__device__ __forceinline__ void load_stage(uint32_t sb, int slot,
                                           int m0, int n0, int k0, int tid) {
    uint32_t abase = sb + slot * STAGE_B;
    uint32_t bbase = abase + A_STAGE_B;
    const char* asrc = reinterpret_cast<const char*>(g_xdq + (size_t)m0 * GK + k0);
    const char* bsrc = reinterpret_cast<const char*>(g_wdq + (size_t)n0 * GK + k0);
    const size_t ROWB = GK * sizeof(__half);   // 4096 B global row stride
    // (BM + BN) rows x 4 c-chunks of 32B each; each iteration = 2 x cp16.
    // Global BYTE offset == smem BYTE offset (pre-swizzle): row*128 + c*32.
    #pragma unroll
    for (int i = tid; i < (BM + BN) * 4; i += 256) {
        uint32_t base;
        const char* src;
        int row = (i >> 2) & 127;
        int c   = i & 3;
        if (i < BM * 4) { base = abase; src = asrc + (size_t)row * ROWB + c * 32; }
        else            { base = bbase; src = bsrc + (size_t)row * ROWB + c * 32; }
        uint32_t off = (uint32_t)(row * 128 + c * 32);
        cp16(base + SMEM_SWIZZLE_128B(off), src);
        cp16(base + SMEM_SWIZZLE_128B(off + 16), src + 16);
    }
    asm volatile("cp.async.commit_group;");
}

__global__ __launch_bounds__(256, 1) void gemm_f16_kernel(
    const float* __restrict__ bias, float* __restrict__ out, int M
) {
    extern __shared__ char smem[];
    uint32_t sb = smem_to_u32(smem);
    int tid  = threadIdx.x;
    int wid  = tid >> 5;
    int lane = tid & 31;
    int wm = wid & 1;          // 0..1 -> 64-row slab
    int wn = wid >> 1;         // 0..3 -> 32-col slab
    int m0 = blockIdx.y * BM;
    int n0 = blockIdx.x * BN;

    // ldmatrix lane address components (same pattern for A and B tiles):
    // row-in-16 = (lane&7) + 8*((lane>>3)&1), col8 = ((lane>>4)&1)*8
    int lrow = (lane & 7) + (((lane >> 3) & 1) << 3);
    int lc8  = ((lane >> 4) & 1) << 3;

    float acc[4][4][4];   // [mt][nt(n8)][4]
    #pragma unroll
    for (int i = 0; i < 4; i++)
        #pragma unroll
        for (int j = 0; j < 4; j++)
            #pragma unroll
            for (int q = 0; q < 4; q++) acc[i][j][q] = 0.0f;

    const int KS = GK / BK;   // 32

    #pragma unroll
    for (int s = 0; s < STAGES - 1; s++)
        load_stage(sb, s, m0, n0, s * BK, tid);

    for (int ks = 0; ks < KS; ks++) {
        int slot = ks % STAGES;
        asm volatile("cp.async.wait_group %0;" :: "n"(STAGES - 2));
        __syncthreads();

        uint32_t abase = sb + slot * STAGE_B;
        uint32_t bbase = abase + A_STAGE_B;

        #pragma unroll
        for (int kk = 0; kk < BK / 16; kk++) {
            uint32_t a[4][4];
            #pragma unroll
            for (int mt = 0; mt < 4; mt++) {
                uint32_t off = (uint32_t)((wm * 64 + mt * 16 + lrow) * 128
                                          + (kk * 16 + lc8) * 2);
                ldsm4(a[mt][0], a[mt][1], a[mt][2], a[mt][3],
                      abase + SMEM_SWIZZLE_128B(off));
            }
            uint32_t b[2][4];
            #pragma unroll
            for (int bt = 0; bt < 2; bt++) {
                uint32_t off = (uint32_t)((wn * 32 + bt * 16 + lrow) * 128
                                          + (kk * 16 + lc8) * 2);
                ldsm4(b[bt][0], b[bt][1], b[bt][2], b[bt][3],
                      bbase + SMEM_SWIZZLE_128B(off));
            }
            #pragma unroll
            for (int mt = 0; mt < 4; mt++) {
                #pragma unroll
                for (int bt = 0; bt < 2; bt++) {
                    // low-n 8 cols of the 16-block: B regs (r0, r2)
                    mma16816(acc[mt][bt * 2 + 0],
                             a[mt][0], a[mt][1], a[mt][2], a[mt][3],
                             b[bt][0], b[bt][2]);
                    // high-n 8 cols: B regs (r1, r3)
                    mma16816(acc[mt][bt * 2 + 1],
                             a[mt][0], a[mt][1], a[mt][2], a[mt][3],
                             b[bt][1], b[bt][3]);
                }
            }
        }

        __syncthreads();
        int nk = ks + STAGES - 1;
        if (nk < KS) {
            load_stage(sb, nk % STAGES, m0, n0, nk * BK, tid);
        } else {
            asm volatile("cp.async.commit_group;");  // keep group count moving
        }
    }

    // Epilogue: scale + bias, f32 output
    int qrow = lane >> 2;          // 0..7
    int qcol = (lane & 3) * 2;     // 0,2,4,6
    #pragma unroll
    for (int mt = 0; mt < 4; mt++) {
        int r0 = m0 + wm * 64 + mt * 16 + qrow;
        #pragma unroll
        for (int nt = 0; nt < 4; nt++) {
            int col = n0 + wn * 32 + (nt >> 1) * 16 + (nt & 1) * 8 + qcol;
            float b0 = bias[col], b1 = bias[col + 1];
            float2 v0, v1;
            v0.x = acc[mt][nt][0] * OUT_SCALE + b0;
            v0.y = acc[mt][nt][1] * OUT_SCALE + b1;
            v1.x = acc[mt][nt][2] * OUT_SCALE + b0;
            v1.y = acc[mt][nt][3] * OUT_SCALE + b1;
            *reinterpret_cast<float2*>(out + (size_t)r0 * GN + col) = v0;
            *reinterpret_cast<float2*>(out + (size_t)(r0 + 8) * GN + col) = v1;
        }
    }
}

// ============================================================================
// Launch
// ============================================================================
extern "C" void kernel_launch(void* const* d_in, const int* in_sizes, int n_in,
                              void* d_out, int out_size) {
    const float* x    = (const float*)d_in[0];
    const float* w    = (const float*)d_in[1];
    const float* ws   = (const float*)d_in[2];
    const float* bias = (const float*)d_in[3];
    float* out = (float*)d_out;

    int O = in_sizes[3];               // 2048
    int H = in_sizes[1] / O;           // 2048
    int M = in_sizes[0] / H;           // 16384
    int ngroups = M * (H / 128);

    quant_x_kernel<<<(ngroups + 7) / 8, 256>>>(x, ngroups);
    dequant_w_kernel<<<(O * H / 4 + 255) / 256, 256>>>(w, ws);

    cudaFuncSetAttribute(gemm_f16_kernel,
                         cudaFuncAttributeMaxDynamicSharedMemorySize, SMEM_TOTAL);
    dim3 grid(GN / BN, M / BM);        // (16, 128): n fastest -> A reuse in L2
    gemm_f16_kernel<<<grid, 256, SMEM_TOTAL>>>(bias, out, M);
}